// round 13
// baseline (speedup 1.0000x reference)
#include <cuda_runtime.h>
#include <cuda_fp16.h>
#include <cstdint>

#define TT    128
#define BB_   64
#define SS_   128
#define VV    8000
#define VP    8064
#define EMBD  256
#define ENCD  512
#define DECD  512
#define HEH   20
#define KXD   1280   // EMB + DEC + ENC
#define NBLK  128    // loop blocks

// X row r = t*64 + b, layout: [ emb(0:256) | new_hidden(256:768) | context(768:1280) ]
__device__ alignas(16) float  g_X [(size_t)TT * BB_ * KXD];
__device__ alignas(16) __half g_Xh[(size_t)TT * BB_ * KXD];
__device__ alignas(16) __half g_WhT[(size_t)VP * KXD];
__device__ alignas(16) float  g_encpart[(size_t)BB_ * SS_ * HEH];
__device__ alignas(16) float  g_wdump[(size_t)BB_ * TT * SS_];
__device__ alignas(16) float  g_part[(size_t)16 * BB_ * DECD];
__device__ int g_bar;

__device__ __forceinline__ float eluf(float x) { return x > 0.f ? x : expm1f(x); }

#define FMA2(a, x, w) asm("fma.rn.f32x2 %0, %1, %2, %0;" : "+l"(a) : "l"(x), "l"(w))

// ---------------------------------------------------------------------------
// P1: gather embedding rows for all (t,b)
// ---------------------------------------------------------------------------
__global__ void k_gather(const int* __restrict__ real_output, const float* __restrict__ emb)
{
    int idx = blockIdx.x * 256 + threadIdx.x;
    int r  = idx >> 6;
    int e4 = idx & 63;
    int t = r >> 6;
    int b = r & 63;
    int tok = (t == 0) ? 0 : real_output[b * TT + (t - 1)];
    tok = ((tok % VV) + VV) % VV;
    float4 v = *(const float4*)(emb + (size_t)tok * EMBD + e4 * 4);
    size_t o = (size_t)r * KXD + e4 * 4;
    *(float4*)(g_X + o) = v;
    __half2* xh = (__half2*)(g_Xh + o);
    xh[0] = __floats2half2_rn(v.x, v.y);
    xh[1] = __floats2half2_rn(v.z, v.w);
}

// ---------------------------------------------------------------------------
// P2: enc_part[b,s,:] = enc_hid[b,s,:] @ W_e1[0:512,:] + b_e1
// ---------------------------------------------------------------------------
__global__ void k_encpart(const float* __restrict__ enc_hid, const float* __restrict__ W_e1,
                          const float* __restrict__ b_e1)
{
    int gw   = (blockIdx.x * 256 + threadIdx.x) >> 5;
    int lane = threadIdx.x & 31;
    int b = gw >> 7, s = gw & 127;
    const float* er = enc_hid + ((size_t)b * SS_ + s) * ENCD;
    float p[HEH];
#pragma unroll
    for (int h = 0; h < HEH; h++) p[h] = 0.f;
    for (int c = lane; c < ENCD; c += 32) {
        float x = er[c];
        const float* wr = W_e1 + (size_t)c * HEH;
#pragma unroll
        for (int h = 0; h < HEH; h++) p[h] += x * wr[h];
    }
#pragma unroll
    for (int h = 0; h < HEH; h++) {
        float v = p[h];
        v += __shfl_down_sync(0xffffffffu, v, 16);
        v += __shfl_down_sync(0xffffffffu, v, 8);
        v += __shfl_down_sync(0xffffffffu, v, 4);
        v += __shfl_down_sync(0xffffffffu, v, 2);
        v += __shfl_down_sync(0xffffffffu, v, 1);
        if (lane == 0) g_encpart[((size_t)b * SS_ + s) * HEH + h] = v + b_e1[h];
    }
}

// ---------------------------------------------------------------------------
// P3: W_out [1280][8000] fp32 -> g_WhT [8064][1280] fp16
// ---------------------------------------------------------------------------
__global__ void k_wtrans(const float* __restrict__ W_out)
{
    __shared__ float tile[32][33];
    int k0 = blockIdx.x * 32, n0 = blockIdx.y * 32;
    int tx = threadIdx.x, ty = threadIdx.y;
    int n = n0 + tx;
    for (int j = ty; j < 32; j += 8)
        tile[j][tx] = (n < VV) ? W_out[(size_t)(k0 + j) * VV + n] : 0.f;
    __syncthreads();
    for (int j = ty; j < 32; j += 8)
        g_WhT[(size_t)(n0 + j) * KXD + k0 + tx] = __float2half(tile[tx][j]);
}

// ---------------------------------------------------------------------------
// Flat grid barrier (measured-best design)
// ---------------------------------------------------------------------------
__device__ __forceinline__ void grid_barrier(int target)
{
    __syncthreads();
    if (threadIdx.x == 0) {
        asm volatile("red.release.gpu.global.add.s32 [%0], 1;" :: "l"(&g_bar));
        int v;
        do {
            asm volatile("ld.global.acquire.gpu.b32 %0, [%1];" : "=r"(v) : "l"(&g_bar));
        } while (v < target);
    }
    __syncthreads();
}

// dynamic smem layout (floats)
#define OFF_W1   0            // [20][512]
#define OFF_ENC  10240        // [128][21]
#define OFF_BRNN 12928        // [512]
#define OFF_HID  13440        // [512]
#define OFF_E    13952        // [128]
#define OFF_HP   14080        // [20]
#define OFF_W2   14100        // [20]
#define OFF_RED  14120        // [12]
#define OFF_SC   14132        // [4]
#define OFF_XS   14136        // [64][81]
#define OFF_WS   19320        // [80][64]
#define OFF_ENCH 24440        // enc_hid[b] as fp16: 128x512 halves = 32768 float-slots
#define SMEM_FLOATS 57208     // 228,832 bytes: loop SMs have no room for a k_out CTA

__global__ __launch_bounds__(256, 1) void k_loop(
    const float* __restrict__ enc_hid, const float* __restrict__ W_e1,
    const float* __restrict__ W_e2,    const float* __restrict__ b_e2,
    const float* __restrict__ W_rnn,   const float* __restrict__ b_rnn,
    float* __restrict__ wout)
{
    extern __shared__ float sm[];
    float* W1s   = sm + OFF_W1;
    float* encp  = sm + OFF_ENC;
    float* brnns = sm + OFF_BRNN;
    float* hid   = sm + OFF_HID;
    float* sh_e  = sm + OFF_E;
    float* hproj = sm + OFF_HP;
    float* w2s   = sm + OFF_W2;
    float* red   = sm + OFF_RED;
    float* scal  = sm + OFF_SC;
    float* Xs    = sm + OFF_XS;
    float* Ws    = sm + OFF_WS;
    __half2* ench = (__half2*)(sm + OFF_ENCH);

    // allow the PDL-serialized k_out to begin filling the free SMs
    cudaTriggerProgrammaticLaunchCompletion();

    const int tid = threadIdx.x, bid = blockIdx.x;
    const int b = bid;
    const int nc = bid >> 4, kc = bid & 15;
    const int k0 = kc * 80;
    int bar = 0;

    if (bid < BB_) {
        for (int i = tid; i < HEH * 512; i += 256) {
            int h = i >> 9, k = i & 511;
            W1s[i] = W_e1[(size_t)(ENCD + k) * HEH + h];
        }
        for (int i = tid; i < SS_ * HEH; i += 256) {
            int s = i / HEH, h = i % HEH;
            encp[s * 21 + h] = g_encpart[((size_t)b * SS_ + s) * HEH + h];
        }
        for (int i = tid; i < DECD; i += 256) brnns[i] = b_rnn[i];
        if (tid < HEH) w2s[tid] = W_e2[tid];
        if (tid == 0)  scal[0] = b_e2[0];
        const float2* eb = (const float2*)(enc_hid + (size_t)b * SS_ * ENCD);
        for (int i = tid; i < SS_ * ENCD / 2; i += 256) {
            float2 v = eb[i];
            ench[i] = __floats2half2_rn(v.x, v.y);
        }
    }
    for (int i = tid; i < 1280; i += 256) {
        int kk = i >> 4, q = i & 15;
        float4 v = *(const float4*)(W_rnn + (size_t)(k0 + kk) * DECD + nc * 64 + q * 4);
        *(float4*)(Ws + kk * 64 + q * 4) = v;
    }

    for (int t = 0; t < TT; t++) {
        // ---------------- Phase A ----------------
        if (bid < BB_) {
            if (t == 0) {
                hid[tid] = 0.f; hid[tid + 256] = 0.f;
            } else {
#pragma unroll
                for (int rr = 0; rr < 2; rr++) {
                    int c = tid + rr * 256;
                    float s = brnns[c];
#pragma unroll
                    for (int kci = 0; kci < 16; kci++)
                        s += g_part[((size_t)kci * BB_ + b) * DECD + c];
                    float h = eluf(s);
                    hid[c] = h;
                    size_t o = (size_t)((t - 1) * BB_ + b) * KXD + EMBD + c;
                    g_X[o]  = h;
                    g_Xh[o] = __float2half(h);
                }
            }
            __syncthreads();

            {
                int w = tid >> 5, lane = tid & 31;
                for (int h = w; h < HEH; h += 8) {
                    float acc = 0.f;
#pragma unroll
                    for (int k = lane; k < DECD; k += 32) acc += hid[k] * W1s[h * 512 + k];
                    acc += __shfl_down_sync(0xffffffffu, acc, 16);
                    acc += __shfl_down_sync(0xffffffffu, acc, 8);
                    acc += __shfl_down_sync(0xffffffffu, acc, 4);
                    acc += __shfl_down_sync(0xffffffffu, acc, 2);
                    acc += __shfl_down_sync(0xffffffffu, acc, 1);
                    if (lane == 0) hproj[h] = acc;
                }
            }
            __syncthreads();

            if (tid < SS_) {
                float acc = 0.f;
#pragma unroll
                for (int h = 0; h < HEH; h++)
                    acc += eluf(encp[tid * 21 + h] + hproj[h]) * w2s[h];
                sh_e[tid] = expf(eluf(acc + scal[0]));
            }
            __syncthreads();
            {
                float v = (tid < SS_) ? sh_e[tid] : 0.f;
#pragma unroll
                for (int o = 16; o > 0; o >>= 1) v += __shfl_down_sync(0xffffffffu, v, o);
                if ((tid & 31) == 0) red[tid >> 5] = v;
            }
            __syncthreads();
            if (tid == 0) red[8] = 1.f / (red[0] + red[1] + red[2] + red[3]);
            __syncthreads();
            float inv = red[8];
            if (tid < SS_) {
                float w = sh_e[tid] * inv;
                sh_e[tid] = w;
                wout[((size_t)b * TT + t) * SS_ + tid] = w;
            }
            __syncthreads();

            // context from smem-resident fp16 enc (LDS-only chain)
            {
                float a0 = 0.f, a1 = 0.f;
                const __half2* ep = ench + tid;
#pragma unroll 16
                for (int s = 0; s < SS_; s++) {
                    float w = sh_e[s];
                    float2 v = __half22float2(ep[s * 256]);
                    a0 += w * v.x; a1 += w * v.y;
                }
                size_t ro = (size_t)(t * BB_ + b) * KXD + (EMBD + DECD) + 2 * tid;
                g_X[ro] = a0; g_X[ro + 1] = a1;
                *(__half2*)(g_Xh + ro) = __floats2half2_rn(a0, a1);
            }
        }
        bar += NBLK; grid_barrier(bar);

        // ---------------- Phase B ----------------
        {
            for (int i = tid; i < 1280; i += 256) {
                int r = i & 63, q = i >> 6;
                int k = k0 + q * 4;
                bool hseg = (k >= EMBD && k < EMBD + DECD);
                float4 v;
                if (hseg && t == 0) { v.x = v.y = v.z = v.w = 0.f; }
                else {
                    int row = (hseg ? (t - 1) : t) * BB_ + r;
                    v = *(const float4*)(g_X + (size_t)row * KXD + k);
                }
                float* d = Xs + r * 81 + q * 4;
                d[0] = v.x; d[1] = v.y; d[2] = v.z; d[3] = v.w;
            }
            __syncthreads();

            int bb = tid & 63, cg = tid >> 6;
            const float* xsrc = Xs + bb * 81;
            const float* wsrc = Ws + cg * 16;
            unsigned long long acc[8];
#pragma unroll
            for (int j = 0; j < 8; j++) acc[j] = 0ull;
#pragma unroll 4
            for (int k = 0; k < 80; k++) {
                float xv = xsrc[k];
                unsigned long long xx;
                asm("mov.b64 %0, {%1, %1};" : "=l"(xx) : "f"(xv));
                const ulonglong2* wp = (const ulonglong2*)(wsrc + (size_t)k * 64);
                ulonglong2 w01 = wp[0];
                ulonglong2 w23 = wp[1];
                ulonglong2 w45 = wp[2];
                ulonglong2 w67 = wp[3];
                FMA2(acc[0], xx, w01.x); FMA2(acc[1], xx, w01.y);
                FMA2(acc[2], xx, w23.x); FMA2(acc[3], xx, w23.y);
                FMA2(acc[4], xx, w45.x); FMA2(acc[5], xx, w45.y);
                FMA2(acc[6], xx, w67.x); FMA2(acc[7], xx, w67.y);
            }
            float* gp = g_part + ((size_t)kc * BB_ + bb) * DECD + nc * 64 + cg * 16;
#pragma unroll
            for (int j = 0; j < 8; j++) {
                unsigned int lo, hi;
                asm("mov.b64 {%0, %1}, %2;" : "=r"(lo), "=r"(hi) : "l"(acc[j]));
                gp[2 * j]     = __uint_as_float(lo);
                gp[2 * j + 1] = __uint_as_float(hi);
            }
            __syncthreads();
        }
        bar += NBLK; grid_barrier(bar);
    }

    // epilogue: hidden(127), then final publish barrier for band 63
    if (bid < BB_) {
#pragma unroll
        for (int rr = 0; rr < 2; rr++) {
            int c = tid + rr * 256;
            float s = brnns[c];
#pragma unroll
            for (int kci = 0; kci < 16; kci++)
                s += g_part[((size_t)kci * BB_ + b) * DECD + c];
            float h = eluf(s);
            size_t o = (size_t)(127 * BB_ + b) * KXD + EMBD + c;
            g_X[o]  = h;
            g_Xh[o] = __float2half(h);
        }
    }
    bar += NBLK; grid_barrier(bar);   // g_bar = 257*NBLK
}

// ---------------------------------------------------------------------------
// K3: final GEMM out = elu(X @ WhT^T + b_out), mma.sync fp16, 3-stage pipeline.
// Launched with PDL: blocks may start during k_loop (on the 20 free SMs) and
// poll g_bar for their M-band's readiness before reading g_Xh.
// ---------------------------------------------------------------------------
#define MMA16816(C, A0, A1, A2, A3, B0, B1)                                          \
    asm volatile("mma.sync.aligned.m16n8k16.row.col.f32.f16.f16.f32 "                \
                 "{%0,%1,%2,%3},{%4,%5,%6,%7},{%8,%9},{%0,%1,%2,%3};"                \
                 : "+f"(C[0]), "+f"(C[1]), "+f"(C[2]), "+f"(C[3])                    \
                 : "r"(A0), "r"(A1), "r"(A2), "r"(A3), "r"(B0), "r"(B1))

#define KTILES    40
#define STG_HALFS (128 * 40)
#define KOUT_SMEM (3 * 2 * STG_HALFS * 2)    // 61440 bytes

__global__ __launch_bounds__(256) void k_out(const float* __restrict__ b_out,
                                             float* __restrict__ outp)
{
    extern __shared__ __align__(16) __half hsm[];
    const int tid = threadIdx.x;
    const int warp = tid >> 5, lane = tid & 31;
    const int wm = (warp & 3) * 32, wn = (warp >> 2) * 64;
    const int r0 = blockIdx.x * 128, n0 = blockIdx.y * 128;

    // band readiness: rows [r0, r0+128) = t in [2j, 2j+2); hidden(2j+1) is
    // published at g_bar >= (4j+5)*NBLK (epilogue band: 257*NBLK)
    if (tid == 0) {
        int j = blockIdx.x;
        int need = (j == 63) ? 257 * NBLK : (4 * j + 5) * NBLK;
        int v;
        do {
            asm volatile("ld.global.acquire.gpu.b32 %0, [%1];" : "=r"(v) : "l"(&g_bar));
            if (v < need) __nanosleep(1024);
        } while (v < need);
    }
    __syncthreads();

    float acc[2][8][4];
#pragma unroll
    for (int mi = 0; mi < 2; mi++)
#pragma unroll
        for (int ni = 0; ni < 8; ni++)
#pragma unroll
            for (int q = 0; q < 4; q++) acc[mi][ni][q] = 0.f;

    auto ldst = [&](int kt) {
        int st = kt % 3;
        int k0 = kt * 32;
        __half* As = hsm + st * 2 * STG_HALFS;
        __half* Bs = As + STG_HALFS;
#pragma unroll
        for (int i = 0; i < 2; i++) {
            int c = tid + i * 256;
            int row = c >> 2, q8 = (c & 3) * 8;
            uint32_t da = (uint32_t)__cvta_generic_to_shared(As + row * 40 + q8);
            const __half* sa = g_Xh + (size_t)(r0 + row) * KXD + k0 + q8;
            asm volatile("cp.async.cg.shared.global [%0],[%1],16;\n" :: "r"(da), "l"(sa));
            uint32_t db = (uint32_t)__cvta_generic_to_shared(Bs + row * 40 + q8);
            const __half* sb = g_WhT + (size_t)(n0 + row) * KXD + k0 + q8;
            asm volatile("cp.async.cg.shared.global [%0],[%1],16;\n" :: "r"(db), "l"(sb));
        }
        asm volatile("cp.async.commit_group;\n");
    };

    ldst(0); ldst(1);

    for (int kt = 0; kt < KTILES; ++kt) {
        int cur = kt % 3;
        __half* As = hsm + cur * 2 * STG_HALFS;
        __half* Bs = As + STG_HALFS;
        if (kt < KTILES - 1) asm volatile("cp.async.wait_group 1;\n");
        else                 asm volatile("cp.async.wait_group 0;\n");
        __syncthreads();
        if (kt + 2 < KTILES) ldst(kt + 2);

#pragma unroll
        for (int kk = 0; kk < 32; kk += 16) {
            uint32_t a[2][4], bf[4][4];
#pragma unroll
            for (int mi = 0; mi < 2; mi++) {
                int row = wm + mi * 16 + (lane & 15);
                int col = kk + (lane >> 4) * 8;
                uint32_t ad = (uint32_t)__cvta_generic_to_shared(As + row * 40 + col);
                asm volatile("ldmatrix.sync.aligned.m8n8.x4.shared.b16 {%0,%1,%2,%3},[%4];"
                             : "=r"(a[mi][0]), "=r"(a[mi][1]), "=r"(a[mi][2]), "=r"(a[mi][3])
                             : "r"(ad));
            }
#pragma unroll
            for (int nj = 0; nj < 4; nj++) {
                int row = wn + nj * 16 + (lane & 7) + ((lane >> 4) << 3);
                int col = kk + ((lane >> 3) & 1) * 8;
                uint32_t bd = (uint32_t)__cvta_generic_to_shared(Bs + row * 40 + col);
                asm volatile("ldmatrix.sync.aligned.m8n8.x4.shared.b16 {%0,%1,%2,%3},[%4];"
                             : "=r"(bf[nj][0]), "=r"(bf[nj][1]), "=r"(bf[nj][2]), "=r"(bf[nj][3])
                             : "r"(bd));
            }
#pragma unroll
            for (int mi = 0; mi < 2; mi++)
#pragma unroll
                for (int nj = 0; nj < 4; nj++) {
                    MMA16816(acc[mi][2 * nj],     a[mi][0], a[mi][1], a[mi][2], a[mi][3],
                             bf[nj][0], bf[nj][1]);
                    MMA16816(acc[mi][2 * nj + 1], a[mi][0], a[mi][1], a[mi][2], a[mi][3],
                             bf[nj][2], bf[nj][3]);
                }
        }
    }

    // epilogue: bias + elu, map row r=t*64+b -> out[(b*128+t)*8000 + n]
#pragma unroll
    for (int ni = 0; ni < 8; ++ni) {
        int n = n0 + wn + ni * 8 + (lane & 3) * 2;
        if (n >= VV) continue;
        float bo0 = b_out[n], bo1 = b_out[n + 1];
#pragma unroll
        for (int mi = 0; mi < 2; mi++) {
            int gr = r0 + wm + mi * 16 + (lane >> 2);
            size_t ob = ((size_t)(gr & 63) * TT + (gr >> 6)) * VV;
            float2 v0;
            v0.x = eluf(acc[mi][ni][0] + bo0);
            v0.y = eluf(acc[mi][ni][1] + bo1);
            *(float2*)(outp + ob + n) = v0;
            int gr2 = gr + 8;
            size_t ob2 = ((size_t)(gr2 & 63) * TT + (gr2 >> 6)) * VV;
            float2 v1;
            v1.x = eluf(acc[mi][ni][2] + bo0);
            v1.y = eluf(acc[mi][ni][3] + bo1);
            *(float2*)(outp + ob2 + n) = v1;
        }
    }
}

// ---------------------------------------------------------------------------
extern "C" void kernel_launch(void* const* d_in, const int* in_sizes, int n_in,
                              void* d_out, int out_size)
{
    const float* enc_hid     = (const float*)d_in[0];
    const int*   real_output = (const int*)  d_in[1];
    const float* W_e1        = (const float*)d_in[2];
    const float* b_e1        = (const float*)d_in[3];
    const float* W_e2        = (const float*)d_in[4];
    const float* b_e2        = (const float*)d_in[5];
    const float* emb         = (const float*)d_in[6];
    const float* W_rnn       = (const float*)d_in[7];
    const float* b_rnn       = (const float*)d_in[8];
    const float* W_out       = (const float*)d_in[9];
    const float* b_out       = (const float*)d_in[10];
    float* outp = (float*)d_out;

    cudaFuncSetAttribute(k_loop, cudaFuncAttributeMaxDynamicSharedMemorySize,
                         SMEM_FLOATS * 4);
    cudaFuncSetAttribute(k_out, cudaFuncAttributeMaxDynamicSharedMemorySize,
                         KOUT_SMEM);

    void* baddr = nullptr;
    cudaGetSymbolAddress(&baddr, g_bar);
    cudaMemsetAsync(baddr, 0, sizeof(int));

    k_gather<<<2048, 256>>>(real_output, emb);
    k_encpart<<<1024, 256>>>(enc_hid, W_e1, b_e1);
    k_wtrans<<<dim3(40, 252), dim3(32, 8)>>>(W_out);

    size_t need = (size_t)BB_ * TT * VV + (size_t)BB_ * TT * SS_;
    float* wptr = ((size_t)out_size >= need) ? (outp + (size_t)BB_ * TT * VV) : g_wdump;

    k_loop<<<NBLK, 256, SMEM_FLOATS * 4>>>(enc_hid, W_e1, W_e2, b_e2, W_rnn, b_rnn, wptr);

    // k_out with programmatic dependent launch: may begin on idle SMs while
    // k_loop runs; its blocks gate themselves on g_bar band readiness.
    cudaLaunchConfig_t cfg = {};
    cfg.gridDim  = dim3(64, 63, 1);
    cfg.blockDim = dim3(256, 1, 1);
    cfg.dynamicSmemBytes = KOUT_SMEM;
    cfg.stream = 0;
    cudaLaunchAttribute attrs[1];
    attrs[0].id = cudaLaunchAttributeProgrammaticStreamSerialization;
    attrs[0].val.programmaticStreamSerializationAllowed = 1;
    cfg.attrs = attrs;
    cfg.numAttrs = 1;
    cudaLaunchKernelEx(&cfg, k_out, b_out, outp);
}

// round 14
// speedup vs baseline: 1.0730x; 1.0730x over previous
#include <cuda_runtime.h>
#include <cuda_fp16.h>
#include <cstdint>

#define TT    128
#define BB_   64
#define SS_   128
#define VV    8000
#define VP    8064
#define EMBD  256
#define ENCD  512
#define DECD  512
#define HEH   20
#define KXD   1280   // EMB + DEC + ENC
#define NBLK  128    // loop blocks

// X row r = t*64 + b, layout: [ emb(0:256) | new_hidden(256:768) | context(768:1280) ]
__device__ alignas(16) float  g_X [(size_t)TT * BB_ * KXD];
__device__ alignas(16) __half g_Xh[(size_t)TT * BB_ * KXD];
__device__ alignas(16) __half g_WhT[(size_t)VP * KXD];
__device__ alignas(16) float  g_encpart[(size_t)BB_ * SS_ * HEH];
__device__ alignas(16) float  g_wdump[(size_t)BB_ * TT * SS_];
__device__ alignas(16) float  g_part[(size_t)16 * BB_ * DECD];
__device__ int g_bar;

__device__ __forceinline__ float eluf(float x) { return x > 0.f ? x : expm1f(x); }

#define FMA2(a, x, w) asm("fma.rn.f32x2 %0, %1, %2, %0;" : "+l"(a) : "l"(x), "l"(w))

// ---------------------------------------------------------------------------
// P1: gather embedding rows for all (t,b)
// ---------------------------------------------------------------------------
__global__ void k_gather(const int* __restrict__ real_output, const float* __restrict__ emb)
{
    int idx = blockIdx.x * 256 + threadIdx.x;
    int r  = idx >> 6;
    int e4 = idx & 63;
    int t = r >> 6;
    int b = r & 63;
    int tok = (t == 0) ? 0 : real_output[b * TT + (t - 1)];
    tok = ((tok % VV) + VV) % VV;
    float4 v = *(const float4*)(emb + (size_t)tok * EMBD + e4 * 4);
    size_t o = (size_t)r * KXD + e4 * 4;
    *(float4*)(g_X + o) = v;
    __half2* xh = (__half2*)(g_Xh + o);
    xh[0] = __floats2half2_rn(v.x, v.y);
    xh[1] = __floats2half2_rn(v.z, v.w);
}

// ---------------------------------------------------------------------------
// P2: enc_part[b,s,:] = enc_hid[b,s,:] @ W_e1[0:512,:] + b_e1
// ---------------------------------------------------------------------------
__global__ void k_encpart(const float* __restrict__ enc_hid, const float* __restrict__ W_e1,
                          const float* __restrict__ b_e1)
{
    int gw   = (blockIdx.x * 256 + threadIdx.x) >> 5;
    int lane = threadIdx.x & 31;
    int b = gw >> 7, s = gw & 127;
    const float* er = enc_hid + ((size_t)b * SS_ + s) * ENCD;
    float p[HEH];
#pragma unroll
    for (int h = 0; h < HEH; h++) p[h] = 0.f;
    for (int c = lane; c < ENCD; c += 32) {
        float x = er[c];
        const float* wr = W_e1 + (size_t)c * HEH;
#pragma unroll
        for (int h = 0; h < HEH; h++) p[h] += x * wr[h];
    }
#pragma unroll
    for (int h = 0; h < HEH; h++) {
        float v = p[h];
        v += __shfl_down_sync(0xffffffffu, v, 16);
        v += __shfl_down_sync(0xffffffffu, v, 8);
        v += __shfl_down_sync(0xffffffffu, v, 4);
        v += __shfl_down_sync(0xffffffffu, v, 2);
        v += __shfl_down_sync(0xffffffffu, v, 1);
        if (lane == 0) g_encpart[((size_t)b * SS_ + s) * HEH + h] = v + b_e1[h];
    }
}

// ---------------------------------------------------------------------------
// P3: W_out [1280][8000] fp32 -> g_WhT [8064][1280] fp16
// ---------------------------------------------------------------------------
__global__ void k_wtrans(const float* __restrict__ W_out)
{
    __shared__ float tile[32][33];
    int k0 = blockIdx.x * 32, n0 = blockIdx.y * 32;
    int tx = threadIdx.x, ty = threadIdx.y;
    int n = n0 + tx;
    for (int j = ty; j < 32; j += 8)
        tile[j][tx] = (n < VV) ? W_out[(size_t)(k0 + j) * VV + n] : 0.f;
    __syncthreads();
    for (int j = ty; j < 32; j += 8)
        g_WhT[(size_t)(n0 + j) * KXD + k0 + tx] = __float2half(tile[tx][j]);
}

// ---------------------------------------------------------------------------
// Flat grid barrier (measured-best design)
// ---------------------------------------------------------------------------
__device__ __forceinline__ void grid_barrier(int target)
{
    __syncthreads();
    if (threadIdx.x == 0) {
        asm volatile("red.release.gpu.global.add.s32 [%0], 1;" :: "l"(&g_bar));
        int v;
        do {
            asm volatile("ld.global.acquire.gpu.b32 %0, [%1];" : "=r"(v) : "l"(&g_bar));
        } while (v < target);
    }
    __syncthreads();
}

// dynamic smem layout (floats)
#define OFF_W1   0            // [20][512]
#define OFF_ENC  10240        // [128][21]
#define OFF_BRNN 12928        // [512]
#define OFF_HID  13440        // [512]
#define OFF_E    13952        // [128]
#define OFF_HP   14080        // [20]
#define OFF_W2   14100        // [20]
#define OFF_RED  14120        // [12]
#define OFF_SC   14132        // [4]
#define OFF_XS   14136        // [64][81]
#define OFF_WS   19320        // [80][64]
#define OFF_ENCH 24440        // enc_hid[b] as fp16: 128x512 halves = 32768 float-slots
#define SMEM_FLOATS 57208     // 228,832 bytes: loop SMs have no room for a k_out CTA

__global__ __launch_bounds__(256, 1) void k_loop(
    const float* __restrict__ enc_hid, const float* __restrict__ W_e1,
    const float* __restrict__ W_e2,    const float* __restrict__ b_e2,
    const float* __restrict__ W_rnn,   const float* __restrict__ b_rnn,
    float* __restrict__ wout)
{
    extern __shared__ float sm[];
    float* W1s   = sm + OFF_W1;
    float* encp  = sm + OFF_ENC;
    float* brnns = sm + OFF_BRNN;
    float* hid   = sm + OFF_HID;
    float* sh_e  = sm + OFF_E;
    float* hproj = sm + OFF_HP;
    float* w2s   = sm + OFF_W2;
    float* red   = sm + OFF_RED;
    float* scal  = sm + OFF_SC;
    float* Xs    = sm + OFF_XS;
    float* Ws    = sm + OFF_WS;
    __half2* ench = (__half2*)(sm + OFF_ENCH);

    // allow the PDL-serialized k_out to begin filling the free SMs
    cudaTriggerProgrammaticLaunchCompletion();

    const int tid = threadIdx.x, bid = blockIdx.x;
    const int b = bid;
    const int nc = bid >> 4, kc = bid & 15;
    const int k0 = kc * 80;
    int bar = 0;

    if (bid < BB_) {
        for (int i = tid; i < HEH * 512; i += 256) {
            int h = i >> 9, k = i & 511;
            W1s[i] = W_e1[(size_t)(ENCD + k) * HEH + h];
        }
        for (int i = tid; i < SS_ * HEH; i += 256) {
            int s = i / HEH, h = i % HEH;
            encp[s * 21 + h] = g_encpart[((size_t)b * SS_ + s) * HEH + h];
        }
        for (int i = tid; i < DECD; i += 256) brnns[i] = b_rnn[i];
        if (tid < HEH) w2s[tid] = W_e2[tid];
        if (tid == 0)  scal[0] = b_e2[0];
        const float2* eb = (const float2*)(enc_hid + (size_t)b * SS_ * ENCD);
        for (int i = tid; i < SS_ * ENCD / 2; i += 256) {
            float2 v = eb[i];
            ench[i] = __floats2half2_rn(v.x, v.y);
        }
    }
    for (int i = tid; i < 1280; i += 256) {
        int kk = i >> 4, q = i & 15;
        float4 v = *(const float4*)(W_rnn + (size_t)(k0 + kk) * DECD + nc * 64 + q * 4);
        *(float4*)(Ws + kk * 64 + q * 4) = v;
    }

    for (int t = 0; t < TT; t++) {
        // ---------------- Phase A ----------------
        if (bid < BB_) {
            if (t == 0) {
                hid[tid] = 0.f; hid[tid + 256] = 0.f;
            } else {
#pragma unroll
                for (int rr = 0; rr < 2; rr++) {
                    int c = tid + rr * 256;
                    float s = brnns[c];
#pragma unroll
                    for (int kci = 0; kci < 16; kci++)
                        s += g_part[((size_t)kci * BB_ + b) * DECD + c];
                    float h = eluf(s);
                    hid[c] = h;
                    size_t o = (size_t)((t - 1) * BB_ + b) * KXD + EMBD + c;
                    g_X[o]  = h;
                    g_Xh[o] = __float2half(h);
                }
            }
            __syncthreads();

            {
                int w = tid >> 5, lane = tid & 31;
                for (int h = w; h < HEH; h += 8) {
                    float acc = 0.f;
#pragma unroll
                    for (int k = lane; k < DECD; k += 32) acc += hid[k] * W1s[h * 512 + k];
                    acc += __shfl_down_sync(0xffffffffu, acc, 16);
                    acc += __shfl_down_sync(0xffffffffu, acc, 8);
                    acc += __shfl_down_sync(0xffffffffu, acc, 4);
                    acc += __shfl_down_sync(0xffffffffu, acc, 2);
                    acc += __shfl_down_sync(0xffffffffu, acc, 1);
                    if (lane == 0) hproj[h] = acc;
                }
            }
            __syncthreads();

            if (tid < SS_) {
                float acc = 0.f;
#pragma unroll
                for (int h = 0; h < HEH; h++)
                    acc += eluf(encp[tid * 21 + h] + hproj[h]) * w2s[h];
                sh_e[tid] = expf(eluf(acc + scal[0]));
            }
            __syncthreads();
            {
                float v = (tid < SS_) ? sh_e[tid] : 0.f;
#pragma unroll
                for (int o = 16; o > 0; o >>= 1) v += __shfl_down_sync(0xffffffffu, v, o);
                if ((tid & 31) == 0) red[tid >> 5] = v;
            }
            __syncthreads();
            if (tid == 0) red[8] = 1.f / (red[0] + red[1] + red[2] + red[3]);
            __syncthreads();
            float inv = red[8];
            if (tid < SS_) {
                float w = sh_e[tid] * inv;
                sh_e[tid] = w;
                wout[((size_t)b * TT + t) * SS_ + tid] = w;
            }
            __syncthreads();

            // context from smem-resident fp16 enc (LDS-only chain)
            {
                float a0 = 0.f, a1 = 0.f;
                const __half2* ep = ench + tid;
#pragma unroll 16
                for (int s = 0; s < SS_; s++) {
                    float w = sh_e[s];
                    float2 v = __half22float2(ep[s * 256]);
                    a0 += w * v.x; a1 += w * v.y;
                }
                size_t ro = (size_t)(t * BB_ + b) * KXD + (EMBD + DECD) + 2 * tid;
                g_X[ro] = a0; g_X[ro + 1] = a1;
                *(__half2*)(g_Xh + ro) = __floats2half2_rn(a0, a1);
            }
        }
        bar += NBLK; grid_barrier(bar);

        // ---------------- Phase B ----------------
        {
            for (int i = tid; i < 1280; i += 256) {
                int r = i & 63, q = i >> 6;
                int k = k0 + q * 4;
                bool hseg = (k >= EMBD && k < EMBD + DECD);
                float4 v;
                if (hseg && t == 0) { v.x = v.y = v.z = v.w = 0.f; }
                else {
                    int row = (hseg ? (t - 1) : t) * BB_ + r;
                    v = *(const float4*)(g_X + (size_t)row * KXD + k);
                }
                float* d = Xs + r * 81 + q * 4;
                d[0] = v.x; d[1] = v.y; d[2] = v.z; d[3] = v.w;
            }
            __syncthreads();

            int bb = tid & 63, cg = tid >> 6;
            const float* xsrc = Xs + bb * 81;
            const float* wsrc = Ws + cg * 16;
            unsigned long long acc[8];
#pragma unroll
            for (int j = 0; j < 8; j++) acc[j] = 0ull;
#pragma unroll 4
            for (int k = 0; k < 80; k++) {
                float xv = xsrc[k];
                unsigned long long xx;
                asm("mov.b64 %0, {%1, %1};" : "=l"(xx) : "f"(xv));
                const ulonglong2* wp = (const ulonglong2*)(wsrc + (size_t)k * 64);
                ulonglong2 w01 = wp[0];
                ulonglong2 w23 = wp[1];
                ulonglong2 w45 = wp[2];
                ulonglong2 w67 = wp[3];
                FMA2(acc[0], xx, w01.x); FMA2(acc[1], xx, w01.y);
                FMA2(acc[2], xx, w23.x); FMA2(acc[3], xx, w23.y);
                FMA2(acc[4], xx, w45.x); FMA2(acc[5], xx, w45.y);
                FMA2(acc[6], xx, w67.x); FMA2(acc[7], xx, w67.y);
            }
            float* gp = g_part + ((size_t)kc * BB_ + bb) * DECD + nc * 64 + cg * 16;
#pragma unroll
            for (int j = 0; j < 8; j++) {
                unsigned int lo, hi;
                asm("mov.b64 {%0, %1}, %2;" : "=r"(lo), "=r"(hi) : "l"(acc[j]));
                gp[2 * j]     = __uint_as_float(lo);
                gp[2 * j + 1] = __uint_as_float(hi);
            }
            __syncthreads();
        }
        bar += NBLK; grid_barrier(bar);
    }

    // epilogue: hidden(127), then final publish barrier for band 63
    if (bid < BB_) {
#pragma unroll
        for (int rr = 0; rr < 2; rr++) {
            int c = tid + rr * 256;
            float s = brnns[c];
#pragma unroll
            for (int kci = 0; kci < 16; kci++)
                s += g_part[((size_t)kci * BB_ + b) * DECD + c];
            float h = eluf(s);
            size_t o = (size_t)(127 * BB_ + b) * KXD + EMBD + c;
            g_X[o]  = h;
            g_Xh[o] = __float2half(h);
        }
    }
    bar += NBLK; grid_barrier(bar);   // g_bar = 257*NBLK
}

// ---------------------------------------------------------------------------
// K3: final GEMM out = elu(X @ WhT^T + b_out), mma.sync fp16, 3-stage pipeline.
// PDL overlap: grid is (nt, band) so the FIRST scheduled blocks all belong to
// band 0 (ready ~24us into the loop) — resident CTAs on free SMs always have
// runnable work as bands unlock in order.
// ---------------------------------------------------------------------------
#define MMA16816(C, A0, A1, A2, A3, B0, B1)                                          \
    asm volatile("mma.sync.aligned.m16n8k16.row.col.f32.f16.f16.f32 "                \
                 "{%0,%1,%2,%3},{%4,%5,%6,%7},{%8,%9},{%0,%1,%2,%3};"                \
                 : "+f"(C[0]), "+f"(C[1]), "+f"(C[2]), "+f"(C[3])                    \
                 : "r"(A0), "r"(A1), "r"(A2), "r"(A3), "r"(B0), "r"(B1))

#define KTILES    40
#define STG_HALFS (128 * 40)
#define KOUT_SMEM (3 * 2 * STG_HALFS * 2)    // 61440 bytes

__global__ __launch_bounds__(256) void k_out(const float* __restrict__ b_out,
                                             float* __restrict__ outp)
{
    extern __shared__ __align__(16) __half hsm[];
    const int tid = threadIdx.x;
    const int warp = tid >> 5, lane = tid & 31;
    const int wm = (warp & 3) * 32, wn = (warp >> 2) * 64;
    const int jband = blockIdx.y;            // M band (time pair)
    const int r0 = jband * 128, n0 = blockIdx.x * 128;

    // band readiness: rows [r0, r0+128) = t in [2j, 2j+2); hidden(2j+1) is
    // published at g_bar >= (4j+5)*NBLK (last band: 257*NBLK)
    if (tid == 0) {
        int need = (jband == 63) ? 257 * NBLK : (4 * jband + 5) * NBLK;
        int v;
        do {
            asm volatile("ld.global.acquire.gpu.b32 %0, [%1];" : "=r"(v) : "l"(&g_bar));
            if (v < need) __nanosleep(1024);
        } while (v < need);
    }
    __syncthreads();

    float acc[2][8][4];
#pragma unroll
    for (int mi = 0; mi < 2; mi++)
#pragma unroll
        for (int ni = 0; ni < 8; ni++)
#pragma unroll
            for (int q = 0; q < 4; q++) acc[mi][ni][q] = 0.f;

    auto ldst = [&](int kt) {
        int st = kt % 3;
        int k0 = kt * 32;
        __half* As = hsm + st * 2 * STG_HALFS;
        __half* Bs = As + STG_HALFS;
#pragma unroll
        for (int i = 0; i < 2; i++) {
            int c = tid + i * 256;
            int row = c >> 2, q8 = (c & 3) * 8;
            uint32_t da = (uint32_t)__cvta_generic_to_shared(As + row * 40 + q8);
            const __half* sa = g_Xh + (size_t)(r0 + row) * KXD + k0 + q8;
            asm volatile("cp.async.cg.shared.global [%0],[%1],16;\n" :: "r"(da), "l"(sa));
            uint32_t db = (uint32_t)__cvta_generic_to_shared(Bs + row * 40 + q8);
            const __half* sb = g_WhT + (size_t)(n0 + row) * KXD + k0 + q8;
            asm volatile("cp.async.cg.shared.global [%0],[%1],16;\n" :: "r"(db), "l"(sb));
        }
        asm volatile("cp.async.commit_group;\n");
    };

    ldst(0); ldst(1);

    for (int kt = 0; kt < KTILES; ++kt) {
        int cur = kt % 3;
        __half* As = hsm + cur * 2 * STG_HALFS;
        __half* Bs = As + STG_HALFS;
        if (kt < KTILES - 1) asm volatile("cp.async.wait_group 1;\n");
        else                 asm volatile("cp.async.wait_group 0;\n");
        __syncthreads();
        if (kt + 2 < KTILES) ldst(kt + 2);

#pragma unroll
        for (int kk = 0; kk < 32; kk += 16) {
            uint32_t a[2][4], bf[4][4];
#pragma unroll
            for (int mi = 0; mi < 2; mi++) {
                int row = wm + mi * 16 + (lane & 15);
                int col = kk + (lane >> 4) * 8;
                uint32_t ad = (uint32_t)__cvta_generic_to_shared(As + row * 40 + col);
                asm volatile("ldmatrix.sync.aligned.m8n8.x4.shared.b16 {%0,%1,%2,%3},[%4];"
                             : "=r"(a[mi][0]), "=r"(a[mi][1]), "=r"(a[mi][2]), "=r"(a[mi][3])
                             : "r"(ad));
            }
#pragma unroll
            for (int nj = 0; nj < 4; nj++) {
                int row = wn + nj * 16 + (lane & 7) + ((lane >> 4) << 3);
                int col = kk + ((lane >> 3) & 1) * 8;
                uint32_t bd = (uint32_t)__cvta_generic_to_shared(Bs + row * 40 + col);
                asm volatile("ldmatrix.sync.aligned.m8n8.x4.shared.b16 {%0,%1,%2,%3},[%4];"
                             : "=r"(bf[nj][0]), "=r"(bf[nj][1]), "=r"(bf[nj][2]), "=r"(bf[nj][3])
                             : "r"(bd));
            }
#pragma unroll
            for (int mi = 0; mi < 2; mi++)
#pragma unroll
                for (int nj = 0; nj < 4; nj++) {
                    MMA16816(acc[mi][2 * nj],     a[mi][0], a[mi][1], a[mi][2], a[mi][3],
                             bf[nj][0], bf[nj][1]);
                    MMA16816(acc[mi][2 * nj + 1], a[mi][0], a[mi][1], a[mi][2], a[mi][3],
                             bf[nj][2], bf[nj][3]);
                }
        }
    }

    // epilogue: bias + elu, map row r=t*64+b -> out[(b*128+t)*8000 + n]
#pragma unroll
    for (int ni = 0; ni < 8; ++ni) {
        int n = n0 + wn + ni * 8 + (lane & 3) * 2;
        if (n >= VV) continue;
        float bo0 = b_out[n], bo1 = b_out[n + 1];
#pragma unroll
        for (int mi = 0; mi < 2; mi++) {
            int gr = r0 + wm + mi * 16 + (lane >> 2);
            size_t ob = ((size_t)(gr & 63) * TT + (gr >> 6)) * VV;
            float2 v0;
            v0.x = eluf(acc[mi][ni][0] + bo0);
            v0.y = eluf(acc[mi][ni][1] + bo1);
            *(float2*)(outp + ob + n) = v0;
            int gr2 = gr + 8;
            size_t ob2 = ((size_t)(gr2 & 63) * TT + (gr2 >> 6)) * VV;
            float2 v1;
            v1.x = eluf(acc[mi][ni][2] + bo0);
            v1.y = eluf(acc[mi][ni][3] + bo1);
            *(float2*)(outp + ob2 + n) = v1;
        }
    }
}

// ---------------------------------------------------------------------------
extern "C" void kernel_launch(void* const* d_in, const int* in_sizes, int n_in,
                              void* d_out, int out_size)
{
    const float* enc_hid     = (const float*)d_in[0];
    const int*   real_output = (const int*)  d_in[1];
    const float* W_e1        = (const float*)d_in[2];
    const float* b_e1        = (const float*)d_in[3];
    const float* W_e2        = (const float*)d_in[4];
    const float* b_e2        = (const float*)d_in[5];
    const float* emb         = (const float*)d_in[6];
    const float* W_rnn       = (const float*)d_in[7];
    const float* b_rnn       = (const float*)d_in[8];
    const float* W_out       = (const float*)d_in[9];
    const float* b_out       = (const float*)d_in[10];
    float* outp = (float*)d_out;

    cudaFuncSetAttribute(k_loop, cudaFuncAttributeMaxDynamicSharedMemorySize,
                         SMEM_FLOATS * 4);
    cudaFuncSetAttribute(k_out, cudaFuncAttributeMaxDynamicSharedMemorySize,
                         KOUT_SMEM);

    void* baddr = nullptr;
    cudaGetSymbolAddress(&baddr, g_bar);
    cudaMemsetAsync(baddr, 0, sizeof(int));

    k_gather<<<2048, 256>>>(real_output, emb);
    k_encpart<<<1024, 256>>>(enc_hid, W_e1, b_e1);
    k_wtrans<<<dim3(40, 252), dim3(32, 8)>>>(W_out);

    size_t need = (size_t)BB_ * TT * VV + (size_t)BB_ * TT * SS_;
    float* wptr = ((size_t)out_size >= need) ? (outp + (size_t)BB_ * TT * VV) : g_wdump;

    k_loop<<<NBLK, 256, SMEM_FLOATS * 4>>>(enc_hid, W_e1, W_e2, b_e2, W_rnn, b_rnn, wptr);

    // k_out with programmatic dependent launch: blocks start on idle SMs while
    // k_loop runs. Grid is (nt, band): first-scheduled blocks are all band 0.
    cudaLaunchConfig_t cfg = {};
    cfg.gridDim  = dim3(63, 64, 1);
    cfg.blockDim = dim3(256, 1, 1);
    cfg.dynamicSmemBytes = KOUT_SMEM;
    cfg.stream = 0;
    cudaLaunchAttribute attrs[1];
    attrs[0].id = cudaLaunchAttributeProgrammaticStreamSerialization;
    attrs[0].val.programmaticStreamSerializationAllowed = 1;
    cfg.attrs = attrs;
    cfg.numAttrs = 1;
    cudaLaunchKernelEx(&cfg, k_out, b_out, outp);
}

// round 15
// speedup vs baseline: 1.0820x; 1.0084x over previous
#include <cuda_runtime.h>
#include <cuda_fp16.h>
#include <cstdint>

#define TT    128
#define BB_   64
#define SS_   128
#define VV    8000
#define VP    8064
#define EMBD  256
#define ENCD  512
#define DECD  512
#define HEH   20
#define KXD   1280   // EMB + DEC + ENC
#define NBLK  128    // loop blocks

// X row r = t*64 + b, layout: [ emb(0:256) | new_hidden(256:768) | context(768:1280) ]
__device__ alignas(16) float  g_X [(size_t)TT * BB_ * KXD];
__device__ alignas(16) __half g_Xh[(size_t)TT * BB_ * KXD];
__device__ alignas(16) __half g_WhT[(size_t)VP * KXD];
__device__ alignas(16) float  g_encpart[(size_t)BB_ * SS_ * HEH];
__device__ alignas(16) float  g_wdump[(size_t)BB_ * TT * SS_];
__device__ alignas(16) float  g_part[(size_t)16 * BB_ * DECD];
__device__ int g_bar;

__device__ __forceinline__ float eluf(float x) { return x > 0.f ? x : expm1f(x); }

#define FMA2(a, x, w) asm("fma.rn.f32x2 %0, %1, %2, %0;" : "+l"(a) : "l"(x), "l"(w))

// ---------------------------------------------------------------------------
// P1: gather embedding rows for all (t,b)
// ---------------------------------------------------------------------------
__global__ void k_gather(const int* __restrict__ real_output, const float* __restrict__ emb)
{
    int idx = blockIdx.x * 256 + threadIdx.x;
    int r  = idx >> 6;
    int e4 = idx & 63;
    int t = r >> 6;
    int b = r & 63;
    int tok = (t == 0) ? 0 : real_output[b * TT + (t - 1)];
    tok = ((tok % VV) + VV) % VV;
    float4 v = *(const float4*)(emb + (size_t)tok * EMBD + e4 * 4);
    size_t o = (size_t)r * KXD + e4 * 4;
    *(float4*)(g_X + o) = v;
    __half2* xh = (__half2*)(g_Xh + o);
    xh[0] = __floats2half2_rn(v.x, v.y);
    xh[1] = __floats2half2_rn(v.z, v.w);
}

// ---------------------------------------------------------------------------
// P2: enc_part[b,s,:] = enc_hid[b,s,:] @ W_e1[0:512,:] + b_e1
// ---------------------------------------------------------------------------
__global__ void k_encpart(const float* __restrict__ enc_hid, const float* __restrict__ W_e1,
                          const float* __restrict__ b_e1)
{
    int gw   = (blockIdx.x * 256 + threadIdx.x) >> 5;
    int lane = threadIdx.x & 31;
    int b = gw >> 7, s = gw & 127;
    const float* er = enc_hid + ((size_t)b * SS_ + s) * ENCD;
    float p[HEH];
#pragma unroll
    for (int h = 0; h < HEH; h++) p[h] = 0.f;
    for (int c = lane; c < ENCD; c += 32) {
        float x = er[c];
        const float* wr = W_e1 + (size_t)c * HEH;
#pragma unroll
        for (int h = 0; h < HEH; h++) p[h] += x * wr[h];
    }
#pragma unroll
    for (int h = 0; h < HEH; h++) {
        float v = p[h];
        v += __shfl_down_sync(0xffffffffu, v, 16);
        v += __shfl_down_sync(0xffffffffu, v, 8);
        v += __shfl_down_sync(0xffffffffu, v, 4);
        v += __shfl_down_sync(0xffffffffu, v, 2);
        v += __shfl_down_sync(0xffffffffu, v, 1);
        if (lane == 0) g_encpart[((size_t)b * SS_ + s) * HEH + h] = v + b_e1[h];
    }
}

// ---------------------------------------------------------------------------
// P3: W_out [1280][8000] fp32 -> g_WhT [8064][1280] fp16
// ---------------------------------------------------------------------------
__global__ void k_wtrans(const float* __restrict__ W_out)
{
    __shared__ float tile[32][33];
    int k0 = blockIdx.x * 32, n0 = blockIdx.y * 32;
    int tx = threadIdx.x, ty = threadIdx.y;
    int n = n0 + tx;
    for (int j = ty; j < 32; j += 8)
        tile[j][tx] = (n < VV) ? W_out[(size_t)(k0 + j) * VV + n] : 0.f;
    __syncthreads();
    for (int j = ty; j < 32; j += 8)
        g_WhT[(size_t)(n0 + j) * KXD + k0 + tx] = __float2half(tile[tx][j]);
}

// ---------------------------------------------------------------------------
// Flat grid barrier (measured-best design)
// ---------------------------------------------------------------------------
__device__ __forceinline__ void grid_barrier(int target)
{
    __syncthreads();
    if (threadIdx.x == 0) {
        asm volatile("red.release.gpu.global.add.s32 [%0], 1;" :: "l"(&g_bar));
        int v;
        do {
            asm volatile("ld.global.acquire.gpu.b32 %0, [%1];" : "=r"(v) : "l"(&g_bar));
        } while (v < target);
    }
    __syncthreads();
}

// dynamic smem layout (floats)
#define OFF_W1   0            // [20][512]
#define OFF_ENC  10240        // [128][21]
#define OFF_BRNN 12928        // [512]
#define OFF_HID  13440        // [512]
#define OFF_E    13952        // [128]
#define OFF_HP   14080        // [20]
#define OFF_W2   14100        // [20]
#define OFF_RED  14120        // [12]
#define OFF_SC   14132        // [4]
#define OFF_XS   14136        // [64][81]
#define OFF_WS   19320        // [80][64]
#define OFF_ENCH 24440        // enc_hid[b] as fp16: 128x512 halves = 32768 float-slots
#define SMEM_FLOATS 57208     // 228,832 bytes: loop SMs have no room for a k_out CTA

__global__ __launch_bounds__(256, 1) void k_loop(
    const float* __restrict__ enc_hid, const float* __restrict__ W_e1,
    const float* __restrict__ W_e2,    const float* __restrict__ b_e2,
    const float* __restrict__ W_rnn,   const float* __restrict__ b_rnn,
    float* __restrict__ wout)
{
    extern __shared__ float sm[];
    float* W1s   = sm + OFF_W1;
    float* encp  = sm + OFF_ENC;
    float* brnns = sm + OFF_BRNN;
    float* hid   = sm + OFF_HID;
    float* sh_e  = sm + OFF_E;
    float* hproj = sm + OFF_HP;
    float* w2s   = sm + OFF_W2;
    float* red   = sm + OFF_RED;
    float* scal  = sm + OFF_SC;
    float* Xs    = sm + OFF_XS;
    float* Ws    = sm + OFF_WS;
    __half2* ench = (__half2*)(sm + OFF_ENCH);

    // allow the PDL-serialized k_out to begin filling the free SMs
    cudaTriggerProgrammaticLaunchCompletion();

    const int tid = threadIdx.x, bid = blockIdx.x;
    const int b = bid;
    const int nc = bid >> 4, kc = bid & 15;
    const int k0 = kc * 80;
    int bar = 0;

    if (bid < BB_) {
        for (int i = tid; i < HEH * 512; i += 256) {
            int h = i >> 9, k = i & 511;
            W1s[i] = W_e1[(size_t)(ENCD + k) * HEH + h];
        }
        for (int i = tid; i < SS_ * HEH; i += 256) {
            int s = i / HEH, h = i % HEH;
            encp[s * 21 + h] = g_encpart[((size_t)b * SS_ + s) * HEH + h];
        }
        for (int i = tid; i < DECD; i += 256) brnns[i] = b_rnn[i];
        if (tid < HEH) w2s[tid] = W_e2[tid];
        if (tid == 0)  scal[0] = b_e2[0];
        const float2* eb = (const float2*)(enc_hid + (size_t)b * SS_ * ENCD);
        for (int i = tid; i < SS_ * ENCD / 2; i += 256) {
            float2 v = eb[i];
            ench[i] = __floats2half2_rn(v.x, v.y);
        }
    }
    for (int i = tid; i < 1280; i += 256) {
        int kk = i >> 4, q = i & 15;
        float4 v = *(const float4*)(W_rnn + (size_t)(k0 + kk) * DECD + nc * 64 + q * 4);
        *(float4*)(Ws + kk * 64 + q * 4) = v;
    }

    for (int t = 0; t < TT; t++) {
        // ---------------- Phase A ----------------
        if (bid < BB_) {
            if (t == 0) {
                hid[tid] = 0.f; hid[tid + 256] = 0.f;
            } else {
#pragma unroll
                for (int rr = 0; rr < 2; rr++) {
                    int c = tid + rr * 256;
                    float s = brnns[c];
#pragma unroll
                    for (int kci = 0; kci < 16; kci++)
                        s += g_part[((size_t)kci * BB_ + b) * DECD + c];
                    float h = eluf(s);
                    hid[c] = h;
                    size_t o = (size_t)((t - 1) * BB_ + b) * KXD + EMBD + c;
                    g_X[o]  = h;
                    g_Xh[o] = __float2half(h);
                }
            }
            __syncthreads();

            {
                int w = tid >> 5, lane = tid & 31;
                for (int h = w; h < HEH; h += 8) {
                    float acc = 0.f;
#pragma unroll
                    for (int k = lane; k < DECD; k += 32) acc += hid[k] * W1s[h * 512 + k];
                    acc += __shfl_down_sync(0xffffffffu, acc, 16);
                    acc += __shfl_down_sync(0xffffffffu, acc, 8);
                    acc += __shfl_down_sync(0xffffffffu, acc, 4);
                    acc += __shfl_down_sync(0xffffffffu, acc, 2);
                    acc += __shfl_down_sync(0xffffffffu, acc, 1);
                    if (lane == 0) hproj[h] = acc;
                }
            }
            __syncthreads();

            if (tid < SS_) {
                float acc = 0.f;
#pragma unroll
                for (int h = 0; h < HEH; h++)
                    acc += eluf(encp[tid * 21 + h] + hproj[h]) * w2s[h];
                sh_e[tid] = expf(eluf(acc + scal[0]));
            }
            __syncthreads();
            {
                float v = (tid < SS_) ? sh_e[tid] : 0.f;
#pragma unroll
                for (int o = 16; o > 0; o >>= 1) v += __shfl_down_sync(0xffffffffu, v, o);
                if ((tid & 31) == 0) red[tid >> 5] = v;
            }
            __syncthreads();
            if (tid == 0) red[8] = 1.f / (red[0] + red[1] + red[2] + red[3]);
            __syncthreads();
            float inv = red[8];
            if (tid < SS_) {
                float w = sh_e[tid] * inv;
                sh_e[tid] = w;
                wout[((size_t)b * TT + t) * SS_ + tid] = w;
            }
            __syncthreads();

            // context from smem-resident fp16 enc (LDS-only chain)
            {
                float a0 = 0.f, a1 = 0.f;
                const __half2* ep = ench + tid;
#pragma unroll 16
                for (int s = 0; s < SS_; s++) {
                    float w = sh_e[s];
                    float2 v = __half22float2(ep[s * 256]);
                    a0 += w * v.x; a1 += w * v.y;
                }
                size_t ro = (size_t)(t * BB_ + b) * KXD + (EMBD + DECD) + 2 * tid;
                g_X[ro] = a0; g_X[ro + 1] = a1;
                *(__half2*)(g_Xh + ro) = __floats2half2_rn(a0, a1);
            }
        }
        bar += NBLK; grid_barrier(bar);

        // ---------------- Phase B ----------------
        {
            for (int i = tid; i < 1280; i += 256) {
                int r = i & 63, q = i >> 6;
                int k = k0 + q * 4;
                bool hseg = (k >= EMBD && k < EMBD + DECD);
                float4 v;
                if (hseg && t == 0) { v.x = v.y = v.z = v.w = 0.f; }
                else {
                    int row = (hseg ? (t - 1) : t) * BB_ + r;
                    v = *(const float4*)(g_X + (size_t)row * KXD + k);
                }
                float* d = Xs + r * 81 + q * 4;
                d[0] = v.x; d[1] = v.y; d[2] = v.z; d[3] = v.w;
            }
            __syncthreads();

            int bb = tid & 63, cg = tid >> 6;
            const float* xsrc = Xs + bb * 81;
            const float* wsrc = Ws + cg * 16;
            unsigned long long acc[8];
#pragma unroll
            for (int j = 0; j < 8; j++) acc[j] = 0ull;
#pragma unroll 4
            for (int k = 0; k < 80; k++) {
                float xv = xsrc[k];
                unsigned long long xx;
                asm("mov.b64 %0, {%1, %1};" : "=l"(xx) : "f"(xv));
                const ulonglong2* wp = (const ulonglong2*)(wsrc + (size_t)k * 64);
                ulonglong2 w01 = wp[0];
                ulonglong2 w23 = wp[1];
                ulonglong2 w45 = wp[2];
                ulonglong2 w67 = wp[3];
                FMA2(acc[0], xx, w01.x); FMA2(acc[1], xx, w01.y);
                FMA2(acc[2], xx, w23.x); FMA2(acc[3], xx, w23.y);
                FMA2(acc[4], xx, w45.x); FMA2(acc[5], xx, w45.y);
                FMA2(acc[6], xx, w67.x); FMA2(acc[7], xx, w67.y);
            }
            float* gp = g_part + ((size_t)kc * BB_ + bb) * DECD + nc * 64 + cg * 16;
#pragma unroll
            for (int j = 0; j < 8; j++) {
                unsigned int lo, hi;
                asm("mov.b64 {%0, %1}, %2;" : "=r"(lo), "=r"(hi) : "l"(acc[j]));
                gp[2 * j]     = __uint_as_float(lo);
                gp[2 * j + 1] = __uint_as_float(hi);
            }
            __syncthreads();
        }
        bar += NBLK; grid_barrier(bar);
    }

    // epilogue: hidden(127), then final publish barrier for band 63
    if (bid < BB_) {
#pragma unroll
        for (int rr = 0; rr < 2; rr++) {
            int c = tid + rr * 256;
            float s = brnns[c];
#pragma unroll
            for (int kci = 0; kci < 16; kci++)
                s += g_part[((size_t)kci * BB_ + b) * DECD + c];
            float h = eluf(s);
            size_t o = (size_t)(127 * BB_ + b) * KXD + EMBD + c;
            g_X[o]  = h;
            g_Xh[o] = __float2half(h);
        }
    }
    bar += NBLK; grid_barrier(bar);   // g_bar = 257*NBLK
}

// ---------------------------------------------------------------------------
// K3: final GEMM out = elu(X @ WhT^T + b_out), mma.sync fp16, 3-stage pipeline.
// PDL overlap (grid = (nt, band)); __launch_bounds__(256,2) => 2 CTAs/SM to
// fill sync/pipeline gaps and double resident CTAs on the free SMs.
// ---------------------------------------------------------------------------
#define MMA16816(C, A0, A1, A2, A3, B0, B1)                                          \
    asm volatile("mma.sync.aligned.m16n8k16.row.col.f32.f16.f16.f32 "                \
                 "{%0,%1,%2,%3},{%4,%5,%6,%7},{%8,%9},{%0,%1,%2,%3};"                \
                 : "+f"(C[0]), "+f"(C[1]), "+f"(C[2]), "+f"(C[3])                    \
                 : "r"(A0), "r"(A1), "r"(A2), "r"(A3), "r"(B0), "r"(B1))

#define KTILES    40
#define STG_HALFS (128 * 40)
#define KOUT_SMEM (3 * 2 * STG_HALFS * 2)    // 61440 bytes; x2 CTAs = 122,880 fits

__global__ __launch_bounds__(256, 2) void k_out(const float* __restrict__ b_out,
                                                float* __restrict__ outp)
{
    extern __shared__ __align__(16) __half hsm[];
    const int tid = threadIdx.x;
    const int warp = tid >> 5, lane = tid & 31;
    const int wm = (warp & 3) * 32, wn = (warp >> 2) * 64;
    const int jband = blockIdx.y;            // M band (time pair)
    const int r0 = jband * 128, n0 = blockIdx.x * 128;

    // band readiness: rows [r0, r0+128) = t in [2j, 2j+2); hidden(2j+1) is
    // published at g_bar >= (4j+5)*NBLK (last band: 257*NBLK)
    if (tid == 0) {
        int need = (jband == 63) ? 257 * NBLK : (4 * jband + 5) * NBLK;
        int v;
        do {
            asm volatile("ld.global.acquire.gpu.b32 %0, [%1];" : "=r"(v) : "l"(&g_bar));
            if (v < need) __nanosleep(1024);
        } while (v < need);
    }
    __syncthreads();

    float acc[2][8][4];
#pragma unroll
    for (int mi = 0; mi < 2; mi++)
#pragma unroll
        for (int ni = 0; ni < 8; ni++)
#pragma unroll
            for (int q = 0; q < 4; q++) acc[mi][ni][q] = 0.f;

    auto ldst = [&](int kt) {
        int st = kt % 3;
        int k0 = kt * 32;
        __half* As = hsm + st * 2 * STG_HALFS;
        __half* Bs = As + STG_HALFS;
#pragma unroll
        for (int i = 0; i < 2; i++) {
            int c = tid + i * 256;
            int row = c >> 2, q8 = (c & 3) * 8;
            uint32_t da = (uint32_t)__cvta_generic_to_shared(As + row * 40 + q8);
            const __half* sa = g_Xh + (size_t)(r0 + row) * KXD + k0 + q8;
            asm volatile("cp.async.cg.shared.global [%0],[%1],16;\n" :: "r"(da), "l"(sa));
            uint32_t db = (uint32_t)__cvta_generic_to_shared(Bs + row * 40 + q8);
            const __half* sb = g_WhT + (size_t)(n0 + row) * KXD + k0 + q8;
            asm volatile("cp.async.cg.shared.global [%0],[%1],16;\n" :: "r"(db), "l"(sb));
        }
        asm volatile("cp.async.commit_group;\n");
    };

    ldst(0); ldst(1);

    for (int kt = 0; kt < KTILES; ++kt) {
        int cur = kt % 3;
        __half* As = hsm + cur * 2 * STG_HALFS;
        __half* Bs = As + STG_HALFS;
        if (kt < KTILES - 1) asm volatile("cp.async.wait_group 1;\n");
        else                 asm volatile("cp.async.wait_group 0;\n");
        __syncthreads();
        if (kt + 2 < KTILES) ldst(kt + 2);

#pragma unroll
        for (int kk = 0; kk < 32; kk += 16) {
            uint32_t a[2][4], bf[4][4];
#pragma unroll
            for (int mi = 0; mi < 2; mi++) {
                int row = wm + mi * 16 + (lane & 15);
                int col = kk + (lane >> 4) * 8;
                uint32_t ad = (uint32_t)__cvta_generic_to_shared(As + row * 40 + col);
                asm volatile("ldmatrix.sync.aligned.m8n8.x4.shared.b16 {%0,%1,%2,%3},[%4];"
                             : "=r"(a[mi][0]), "=r"(a[mi][1]), "=r"(a[mi][2]), "=r"(a[mi][3])
                             : "r"(ad));
            }
#pragma unroll
            for (int nj = 0; nj < 4; nj++) {
                int row = wn + nj * 16 + (lane & 7) + ((lane >> 4) << 3);
                int col = kk + ((lane >> 3) & 1) * 8;
                uint32_t bd = (uint32_t)__cvta_generic_to_shared(Bs + row * 40 + col);
                asm volatile("ldmatrix.sync.aligned.m8n8.x4.shared.b16 {%0,%1,%2,%3},[%4];"
                             : "=r"(bf[nj][0]), "=r"(bf[nj][1]), "=r"(bf[nj][2]), "=r"(bf[nj][3])
                             : "r"(bd));
            }
#pragma unroll
            for (int mi = 0; mi < 2; mi++)
#pragma unroll
                for (int nj = 0; nj < 4; nj++) {
                    MMA16816(acc[mi][2 * nj],     a[mi][0], a[mi][1], a[mi][2], a[mi][3],
                             bf[nj][0], bf[nj][1]);
                    MMA16816(acc[mi][2 * nj + 1], a[mi][0], a[mi][1], a[mi][2], a[mi][3],
                             bf[nj][2], bf[nj][3]);
                }
        }
    }

    // epilogue: bias + elu, map row r=t*64+b -> out[(b*128+t)*8000 + n]
#pragma unroll
    for (int ni = 0; ni < 8; ++ni) {
        int n = n0 + wn + ni * 8 + (lane & 3) * 2;
        if (n >= VV) continue;
        float bo0 = b_out[n], bo1 = b_out[n + 1];
#pragma unroll
        for (int mi = 0; mi < 2; mi++) {
            int gr = r0 + wm + mi * 16 + (lane >> 2);
            size_t ob = ((size_t)(gr & 63) * TT + (gr >> 6)) * VV;
            float2 v0;
            v0.x = eluf(acc[mi][ni][0] + bo0);
            v0.y = eluf(acc[mi][ni][1] + bo1);
            *(float2*)(outp + ob + n) = v0;
            int gr2 = gr + 8;
            size_t ob2 = ((size_t)(gr2 & 63) * TT + (gr2 >> 6)) * VV;
            float2 v1;
            v1.x = eluf(acc[mi][ni][2] + bo0);
            v1.y = eluf(acc[mi][ni][3] + bo1);
            *(float2*)(outp + ob2 + n) = v1;
        }
    }
}

// ---------------------------------------------------------------------------
extern "C" void kernel_launch(void* const* d_in, const int* in_sizes, int n_in,
                              void* d_out, int out_size)
{
    const float* enc_hid     = (const float*)d_in[0];
    const int*   real_output = (const int*)  d_in[1];
    const float* W_e1        = (const float*)d_in[2];
    const float* b_e1        = (const float*)d_in[3];
    const float* W_e2        = (const float*)d_in[4];
    const float* b_e2        = (const float*)d_in[5];
    const float* emb         = (const float*)d_in[6];
    const float* W_rnn       = (const float*)d_in[7];
    const float* b_rnn       = (const float*)d_in[8];
    const float* W_out       = (const float*)d_in[9];
    const float* b_out       = (const float*)d_in[10];
    float* outp = (float*)d_out;

    cudaFuncSetAttribute(k_loop, cudaFuncAttributeMaxDynamicSharedMemorySize,
                         SMEM_FLOATS * 4);
    cudaFuncSetAttribute(k_out, cudaFuncAttributeMaxDynamicSharedMemorySize,
                         KOUT_SMEM);

    void* baddr = nullptr;
    cudaGetSymbolAddress(&baddr, g_bar);
    cudaMemsetAsync(baddr, 0, sizeof(int));

    k_gather<<<2048, 256>>>(real_output, emb);
    k_encpart<<<1024, 256>>>(enc_hid, W_e1, b_e1);
    k_wtrans<<<dim3(40, 252), dim3(32, 8)>>>(W_out);

    size_t need = (size_t)BB_ * TT * VV + (size_t)BB_ * TT * SS_;
    float* wptr = ((size_t)out_size >= need) ? (outp + (size_t)BB_ * TT * VV) : g_wdump;

    k_loop<<<NBLK, 256, SMEM_FLOATS * 4>>>(enc_hid, W_e1, W_e2, b_e2, W_rnn, b_rnn, wptr);

    // k_out with programmatic dependent launch: blocks start on idle SMs while
    // k_loop runs. Grid is (nt, band): first-scheduled blocks are all band 0.
    cudaLaunchConfig_t cfg = {};
    cfg.gridDim  = dim3(63, 64, 1);
    cfg.blockDim = dim3(256, 1, 1);
    cfg.dynamicSmemBytes = KOUT_SMEM;
    cfg.stream = 0;
    cudaLaunchAttribute attrs[1];
    attrs[0].id = cudaLaunchAttributeProgrammaticStreamSerialization;
    attrs[0].val.programmaticStreamSerializationAllowed = 1;
    cfg.attrs = attrs;
    cfg.numAttrs = 1;
    cudaLaunchKernelEx(&cfg, k_out, b_out, outp);
}